// round 4
// baseline (speedup 1.0000x reference)
#include <cuda_runtime.h>

#define HH 200
#define WW 304
#define CC 256
#define NOUT 7
#define NSAMP 14          // NOUT * RATIO
#define NCORN 28          // 2 * NSAMP
#define WARPS 8
#define CH_PER_BLOCK 64   // CC / CSPLIT
#define CSPLIT 4

__global__ __launch_bounds__(256, 6)
void roi_align_kernel(const float* __restrict__ feat,
                      const float* __restrict__ boxes,
                      float* __restrict__ out)
{
    __shared__ int   s_cx[NCORN];
    __shared__ float s_fx[NSAMP];
    __shared__ int   s_vx[NSAMP];
    __shared__ int   s_rowbase[NCORN];   // s_cy[a] * WW  (lane-uniform)
    __shared__ float s_wy[NCORN];        // separable y weight * validity (lane-uniform)

    const int r   = blockIdx.x;
    const int tid = threadIdx.x;

    // ---- per-ROI bilinear metadata (threads 0..27) ----
    if (tid < 2 * NSAMP) {
        const int axis = tid / NSAMP;     // 0 = y, 1 = x
        const int i    = tid % NSAMP;
        const float b0 = boxes[r * 4 + (axis ? 0 : 1)] * 0.25f;  // x1 / y1
        const float b1 = boxes[r * 4 + (axis ? 2 : 3)] * 0.25f;  // x2 / y2
        const float len = fmaxf(b1 - b0, 1.0f);
        const float t   = b0 + (i + 0.5f) * 0.5f * (len / 7.0f);
        const int size  = axis ? WW : HH;
        const int valid = (t > -1.0f) && (t < (float)size);
        const float tc  = t < 0.0f ? 0.0f : t;
        const float low = floorf(tc);
        int lo, hi; float frac;
        if (low >= (float)(size - 1)) {
            lo = size - 1; hi = size - 1; frac = 0.0f;
        } else {
            lo = (int)low; hi = lo + 1; frac = tc - low;
        }
        if (axis) {
            s_cx[2 * i] = lo; s_cx[2 * i + 1] = hi; s_fx[i] = frac; s_vx[i] = valid;
        } else {
            const float vm = valid ? 1.0f : 0.0f;
            s_rowbase[2 * i]     = lo * WW;
            s_rowbase[2 * i + 1] = hi * WW;
            s_wy[2 * i]     = (1.0f - frac) * vm;
            s_wy[2 * i + 1] = frac * vm;
        }
    }
    __syncthreads();

    const int warp = tid >> 5;
    const int lane = tid & 31;
    const int img  = r >> 9;                       // r / 512
    const int c0 = blockIdx.y * CH_PER_BLOCK;

    // Per-lane x-corner column and separable x weight (frac * validity).
    // Lanes 28-31 mirror lane 27's address (coalesces, weight forced to 0).
    const int cidx = lane < NCORN ? lane : NCORN - 1;
    const int mycx = s_cx[cidx];
    float wx;
    {
        const int sx = cidx >> 1;
        const float fx = s_fx[sx];
        wx = ((cidx & 1) ? fx : 1.0f - fx) * (s_vx[sx] ? 1.0f : 0.0f);
        if (lane >= NCORN) wx = 0.0f;
    }

    // Per-lane base pointer into this image; row offsets stay in smem (uniform)
    const float* fl = feat + (size_t)img * CC * HH * WW + mycx;

    const int px = lane >> 2;                       // x-group id (valid for lane<28)
    const bool writer = (lane < NCORN) && ((lane & 3) == 0);

    for (int c = c0 + warp; c < c0 + CH_PER_BLOCK; c += WARPS) {
        const float* fc = fl + (size_t)c * (HH * WW);

        // y-reduction folded into the gather: acc[py] = sum_a wy[a]*grid[a][lane]
        float acc[NOUT];
        #pragma unroll
        for (int py = 0; py < NOUT; py++) acc[py] = 0.0f;
        #pragma unroll
        for (int a = 0; a < NCORN; a++) {
            acc[a >> 2] = fmaf(s_wy[a], __ldg(fc + s_rowbase[a]), acc[a >> 2]);
        }

        // x weight + butterfly reduce within each 4-lane group (lanes 4px..4px+3)
        float res[NOUT];
        #pragma unroll
        for (int py = 0; py < NOUT; py++) {
            float v = acc[py] * wx;
            v += __shfl_xor_sync(0xffffffffu, v, 1);
            v += __shfl_xor_sync(0xffffffffu, v, 2);
            res[py] = v;
        }

        if (writer) {
            float* ob = out + ((size_t)r * CC + c) * (NOUT * NOUT);
            #pragma unroll
            for (int py = 0; py < NOUT; py++) {
                ob[py * NOUT + px] = res[py] * 0.25f;
            }
        }
    }
}

extern "C" void kernel_launch(void* const* d_in, const int* in_sizes, int n_in,
                              void* d_out, int out_size)
{
    const float* feat  = (const float*)d_in[0];   // (2,256,200,304) f32
    const float* boxes = (const float*)d_in[1];   // (2,512,4) f32
    float* out = (float*)d_out;                   // (1024,256,7,7) f32

    dim3 grid(1024, CSPLIT);
    dim3 block(256);
    roi_align_kernel<<<grid, block>>>(feat, boxes, out);
}

// round 6
// speedup vs baseline: 1.8889x; 1.8889x over previous
#include <cuda_runtime.h>

#define HH 200
#define WW 304
#define CC 256
#define NOUT 7
#define NSAMP 14          // NOUT * RATIO
#define NCORN 28          // 2 * NSAMP
#define TPITCH 36         // padded tile pitch (floats): 16B-aligned, spreads bank quads
#define WARPS 8
#define CH_PER_BLOCK 64   // CC / CSPLIT
#define CSPLIT 4

__global__ __launch_bounds__(256, 4)
void roi_align_kernel(const float* __restrict__ feat,
                      const float* __restrict__ boxes,
                      float* __restrict__ out)
{
    __shared__ int   s_cx[NCORN];
    __shared__ float s_fx[NSAMP];
    __shared__ int   s_vx[NSAMP];
    __shared__ int   s_cy[NCORN];
    __shared__ float s_wy[NCORN];        // separable y weight * validity (lane-uniform)
    __shared__ __align__(16) float tile[WARPS][NOUT * TPITCH];

    const int r   = blockIdx.x;
    const int tid = threadIdx.x;

    // ---- per-ROI bilinear metadata (threads 0..27) ----
    if (tid < 2 * NSAMP) {
        const int axis = tid / NSAMP;     // 0 = y, 1 = x
        const int i    = tid % NSAMP;
        const float b0 = boxes[r * 4 + (axis ? 0 : 1)] * 0.25f;  // x1 / y1
        const float b1 = boxes[r * 4 + (axis ? 2 : 3)] * 0.25f;  // x2 / y2
        const float len = fmaxf(b1 - b0, 1.0f);
        const float t   = b0 + (i + 0.5f) * 0.5f * (len / 7.0f);
        const int size  = axis ? WW : HH;
        const int valid = (t > -1.0f) && (t < (float)size);
        const float tc  = t < 0.0f ? 0.0f : t;
        const float low = floorf(tc);
        int lo, hi; float frac;
        if (low >= (float)(size - 1)) {
            lo = size - 1; hi = size - 1; frac = 0.0f;
        } else {
            lo = (int)low; hi = lo + 1; frac = tc - low;
        }
        if (axis) {
            s_cx[2 * i] = lo; s_cx[2 * i + 1] = hi; s_fx[i] = frac; s_vx[i] = valid;
        } else {
            const float vm = valid ? 1.0f : 0.0f;
            s_cy[2 * i]     = lo;
            s_cy[2 * i + 1] = hi;
            s_wy[2 * i]     = (1.0f - frac) * vm;
            s_wy[2 * i + 1] = frac * vm;
        }
    }
    __syncthreads();

    const int warp = tid >> 5;
    const int lane = tid & 31;
    const int img  = r >> 9;                       // r / 512
    const float* fb = feat + (size_t)img * CC * HH * WW;
    float* tw = tile[warp];
    const int c0 = blockIdx.y * CH_PER_BLOCK;

    // Per-lane x-corner column + separable x weight (frac * validity).
    const int cidx = lane < NCORN ? lane : NCORN - 1;
    const int mycx = s_cx[cidx];
    float wx;
    {
        const int sx = cidx >> 1;
        const float fx = s_fx[sx];
        wx = ((cidx & 1) ? fx : 1.0f - fx) * (s_vx[sx] ? 1.0f : 0.0f);
    }

    // Per-lane absolute row offsets (registers, computed once).
    int rowoff[NCORN];
    #pragma unroll
    for (int a = 0; a < NCORN; a++) rowoff[a] = s_cy[a] * WW + mycx;

    for (int c = c0 + warp; c < c0 + CH_PER_BLOCK; c += WARPS) {
        const float* fc = fb + (size_t)c * (HH * WW);

        // gather + y-fold: pacc[py] = sum_{a=4py..4py+3} wy[a] * f[row_a][mycol]
        float pacc[NOUT];
        #pragma unroll
        for (int py = 0; py < NOUT; py++) pacc[py] = 0.0f;
        if (lane < NCORN) {
            #pragma unroll
            for (int a = 0; a < NCORN; a++) {
                pacc[a >> 2] = fmaf(s_wy[a], __ldg(fc + rowoff[a]), pacc[a >> 2]);
            }
            // fold x weight, store weighted column partials
            #pragma unroll
            for (int py = 0; py < NOUT; py++) {
                tw[py * TPITCH + lane] = pacc[py] * wx;
            }
        }
        __syncwarp();

        // bins: 1 LDS.128 + horizontal add each
        float* ob = out + ((size_t)r * CC + c) * (NOUT * NOUT);
        #pragma unroll
        for (int bb = 0; bb < 2; bb++) {
            const int bin = lane + bb * 32;
            if (bin < NOUT * NOUT) {
                const int py = bin / NOUT;
                const int px = bin - py * NOUT;
                const float4 q = *(const float4*)(tw + py * TPITCH + 4 * px);
                ob[bin] = (q.x + q.y + q.z + q.w) * 0.25f;
            }
        }
        __syncwarp();
    }
}

extern "C" void kernel_launch(void* const* d_in, const int* in_sizes, int n_in,
                              void* d_out, int out_size)
{
    const float* feat  = (const float*)d_in[0];   // (2,256,200,304) f32
    const float* boxes = (const float*)d_in[1];   // (2,512,4) f32
    float* out = (float*)d_out;                   // (1024,256,7,7) f32

    dim3 grid(1024, CSPLIT);
    dim3 block(256);
    roi_align_kernel<<<grid, block>>>(feat, boxes, out);
}